// round 5
// baseline (speedup 1.0000x reference)
#include <cuda_runtime.h>

// Q_net_3736621548252 — CONVERGED at structural floor (~3.2 us).
//
// ── Why the answer is exactly zero ──────────────────────────────────────────
// The generated equivariant message-passing net is degenerate:
//   L1: ef = [zeros(8) | o1(12) | zeros(20)]  -> node channels [8:20) only.
//   L2: out0/out2 read s=g[:,:8], t=g[:,20:40] (exact zeros) -> both zero;
//       only out1 (from v=g[:,8:20]) survives -> again channels [8:20) only.
//   L3: energy head reads ONLY s=g[:,:8] and t=g[:,20:40] -> exact fp32 zeros.
// Every product feeding the output has an exact 0.0f factor with finite
// co-factors, so the reference output is bit-exactly zeros(NF=64).
// Empirically: rel_err = 0.0 on every passing run (R1-R4).
//
// ── Why ~3.2 us is the floor ────────────────────────────────────────────────
//   * d_out is 0xAA-poisoned + re-validated: all 256 B must be written.
//   * Empty capture is rejected (R0): >= 1 graph node mandatory.
//   * Node-type ladder (measured): kernel node 4.58 us > memset node 3.2 us;
//     a copy node would read+write 256 B (strictly more work).
//   * Residual = cudaGraphLaunch + replay overhead; runs land on 3.20/3.26 us
//     (= +/- one ~64 ns harness tick around the fixed replay cost).
//
// History: R1 kernel node 4.58 -> R2 memset node 3.26 (WIN) -> R3/R4 confirm.

extern "C" void kernel_launch(void* const* d_in, const int* in_sizes, int n_in,
                              void* d_out, int out_size) {
    (void)d_in; (void)in_sizes; (void)n_in;
    // Single native graph memset node: 256 B of 0x00 == fp32 0.0f, matching
    // the reference bit-exactly. Graph-capturable, allocation-free, no sync.
    cudaMemsetAsync(d_out, 0, (size_t)out_size * sizeof(float), 0);
}

// round 6
// speedup vs baseline: 1.2157x; 1.2157x over previous
#include <cuda_runtime.h>

// Q_net_3736621548252 — CONVERGED at structural floor (3.2-4.0 us, noise-bound).
//
// ── Why the answer is exactly zero ──────────────────────────────────────────
// The generated equivariant message-passing net is degenerate:
//   L1: ef = [zeros(8) | o1(12) | zeros(20)]  -> node channels [8:20) only.
//   L2: out0/out2 read s=g[:,:8], t=g[:,20:40] (exact zeros) -> both zero;
//       only out1 (from v=g[:,8:20]) survives -> again channels [8:20) only.
//   L3: energy head reads ONLY s=g[:,:8] and t=g[:,20:40] -> exact fp32 zeros.
// Every product feeding the output has an exact 0.0f factor with finite
// co-factors, so the reference output is bit-exactly zeros(NF=64).
// Empirically: rel_err = 0.0 on every passing run (R1-R5).
//
// ── Why this is the floor ───────────────────────────────────────────────────
//   * d_out is 0xAA-poisoned + re-validated: all 256 B must be written.
//   * Empty capture is rejected (R0): >= 1 graph node mandatory.
//   * Node-type ladder (measured): kernel node 4.58 us > memset node ~3.2 us;
//     a copy node would read+write 256 B (strictly more work).
//   * Noise calibration (R3-R5, identical binary): 3.26/3.26/3.20/3.97 us ->
//     environmental band ~[3.2, 4.0] us. No remaining candidate change has a
//     predicted effect above this noise floor.
//
// History: R1 kernel 4.58 -> R2 memset 3.26 (WIN) -> R3-R5 confirm/noise-cal.

extern "C" void kernel_launch(void* const* d_in, const int* in_sizes, int n_in,
                              void* d_out, int out_size) {
    (void)d_in; (void)in_sizes; (void)n_in;
    // Single native graph memset node: 256 B of 0x00 == fp32 0.0f, matching
    // the reference bit-exactly. Graph-capturable, allocation-free, no sync.
    cudaMemsetAsync(d_out, 0, (size_t)out_size * sizeof(float), 0);
}

// round 7
// speedup vs baseline: 1.2400x; 1.0200x over previous
#include <cuda_runtime.h>

// Q_net_3736621548252 — CONVERGED FINAL (mode ~3.26 us, replay-floor-bound).
//
// ── Why the answer is exactly zero ──────────────────────────────────────────
// The generated equivariant message-passing net is degenerate:
//   L1: ef = [zeros(8) | o1(12) | zeros(20)]  -> node channels [8:20) only.
//   L2: out0/out2 read s=g[:,:8], t=g[:,20:40] (exact zeros) -> both zero;
//       only out1 (from v=g[:,8:20]) survives -> again channels [8:20) only.
//   L3: energy head reads ONLY s=g[:,:8] and t=g[:,20:40] -> exact fp32 zeros.
// Every product feeding the output carries an exact 0.0f factor with finite
// co-factors, so the reference output is bit-exactly zeros(NF=64).
// Empirically: rel_err = 0.0 on every passing run (R1-R6).
//
// ── Why this is the floor ───────────────────────────────────────────────────
//   * d_out is 0xAA-poisoned + re-validated: all 256 B must be written.
//   * Empty capture is rejected (R0): >= 1 graph node mandatory.
//   * Node-type ladder (measured): kernel node 4.58 us > memset node 3.26 us;
//     a copy node reads+writes 256 B (strictly more work than memset).
//   * Noise calibration, identical binary (R2-R6):
//     {3.26, 3.26, 3.20, 3.97, 3.26} us -> mode 3.26, env outliers to ~4.0.
//     Residual time = cudaGraphLaunch + replay overhead, outside
//     kernel_launch's control. No remaining lever exceeds the noise floor.
//
// History: R1 kernel node 4.58 -> R2 memset node 3.26 (WIN) -> R3-R6 confirm.

extern "C" void kernel_launch(void* const* d_in, const int* in_sizes, int n_in,
                              void* d_out, int out_size) {
    (void)d_in; (void)in_sizes; (void)n_in;
    // Single native graph memset node: 256 B of 0x00 == fp32 0.0f, matching
    // the reference bit-exactly. Graph-capturable, allocation-free, no sync.
    cudaMemsetAsync(d_out, 0, (size_t)out_size * sizeof(float), 0);
}